// round 7
// baseline (speedup 1.0000x reference)
#include <cuda_runtime.h>
#include <cstdint>

// TinyLSTM: B=64, T=2048, H=256, V=256
// out = [ logits (64*2048*256) | h_n (64*256) | c_n (64*256) ]  (float32)

#define T_SEQ 2048
#define BATCH 64
#define HID   256
#define G4    1024
#define VOCAB 256

#define LOGITS_ELEMS (BATCH * T_SEQ * HID)
#define HPAD 132   // skewed k-chunk stride (floats) -> conflict-free 2-addr LDS

// scratch (static device arrays; no allocation)
__device__ float g_xtab[VOCAB * G4];   // [v][r] = W_ih[r][v] + b_ih[r] + b_hh[r]
__device__ float g_fcwt[HID * VOCAB];  // [k][c] = fc_W[c][k]
__device__ __align__(32) unsigned g_flag[32][8];  // [group][slice] = steps published

// ---- packed f32x2 helpers ----
__device__ __forceinline__ unsigned long long pk2(float a, float b) {
    unsigned long long r;
    asm("mov.b64 %0, {%1, %2};" : "=l"(r) : "f"(a), "f"(b));
    return r;
}
__device__ __forceinline__ void upk2(unsigned long long v, float& a, float& b) {
    asm("mov.b64 {%0, %1}, %2;" : "=f"(a), "=f"(b) : "l"(v));
}
__device__ __forceinline__ void ffma2(unsigned long long& d, unsigned long long a, unsigned long long b) {
    asm("fma.rn.f32x2 %0, %1, %2, %0;" : "+l"(d) : "l"(a), "l"(b));
}
// L2-only vector load (exchange data produced by peer SMs each step)
__device__ __forceinline__ float4 ldcg4(const float* p) {
    float4 v;
    asm volatile("ld.global.cg.v4.f32 {%0,%1,%2,%3}, [%4];"
                 : "=f"(v.x), "=f"(v.y), "=f"(v.z), "=f"(v.w) : "l"(p));
    return v;
}
__device__ __forceinline__ uint4 ld_acq4(const unsigned* p) {
    uint4 v;
    asm volatile("ld.acquire.gpu.global.v4.u32 {%0,%1,%2,%3}, [%4];"
                 : "=r"(v.x), "=r"(v.y), "=r"(v.z), "=r"(v.w) : "l"(p) : "memory");
    return v;
}
__device__ __forceinline__ void st_rel(unsigned* p, unsigned v) {
    asm volatile("st.release.gpu.global.u32 [%0], %1;" :: "l"(p), "r"(v) : "memory");
}

// =====================================================================
// Phase 0: token table (biases folded), fc_W transpose, zero flags
// =====================================================================
__global__ void prep_kernel(const float* __restrict__ W_ih,
                            const float* __restrict__ b_ih,
                            const float* __restrict__ b_hh,
                            const float* __restrict__ fc_W) {
    int idx = blockIdx.x * blockDim.x + threadIdx.x;
    if (idx < VOCAB * G4) {
        int v = idx >> 10;
        int r = idx & 1023;
        g_xtab[v * G4 + r] = W_ih[r * VOCAB + v] + b_ih[r] + b_hh[r];
    }
    if (idx < HID * VOCAB) {
        int k = idx >> 8;
        int c = idx & 255;
        g_fcwt[k * VOCAB + c] = fc_W[c * HID + k];
    }
    if (idx < 256) ((unsigned*)g_flag)[idx] = 0u;
}

// =====================================================================
// Phase 1: persistent LSTM, latency-hiding dual-slot schedule.
// 32 groups x 2 batches; 8 gate-slices per group. CTA c serves slice
// m = c&7 of groups 2p and 2p+1 (p = c>>3) -> SAME W_hh rows, one
// register copy w2[64]. Per step: process slot A then slot B; while
// A's h-exchange round-trips through L2, the CTA computes B.
// Sync: producer st.release(flag=t+1) per slice; consumer polls the 8
// flags of its group with two ld.acquire.v4 (no atomics).
// =====================================================================
__global__ void __launch_bounds__(256, 1)
lstm_kernel(const int* __restrict__ x,
            const float* __restrict__ W_hh,
            float* __restrict__ out) {
    __shared__ __align__(16) float sh_h[2][2][2 * HPAD]; // [slot][bb][chunk*HPAD+j]
    __shared__ float sh_gates[2][128][3];                // [slot][gate*32+j][bb], stride-3
    __shared__ float sh_c[2][2][32];                     // cell state (CTA-private)
    __shared__ int   sh_tok[2][2][2];                    // [slot][phase][bb]

    const int cta = blockIdx.x;
    const int p   = cta >> 3;          // pair id 0..15
    const int m   = cta & 7;           // gate-slice member 0..7
    const int j_base = m * 32;

    const int tid  = threadIdx.x;
    const int r    = tid >> 1;         // local gate row 0..127
    const int q    = tid & 1;          // k-chunk 0..1 (128 k each)
    const int gate = r >> 5;
    const int jj   = r & 31;
    const int r_global = gate * 256 + j_base + jj;   // row of W_hh / xtab

    // --- W_hh slice -> registers as f32x2 (shared by both slots) ---
    unsigned long long w2[64];
    {
        const float4* wr = reinterpret_cast<const float4*>(W_hh + r_global * HID + q * 128);
#pragma unroll
        for (int i = 0; i < 32; i++) {
            float4 v = wr[i];
            w2[2 * i]     = pk2(v.x, v.y);
            w2[2 * i + 1] = pk2(v.z, v.w);
        }
    }
    if (tid < 128) sh_c[tid >> 6][(tid >> 5) & 1][tid & 31] = 0.0f;
    if (tid < 4) {  // first tokens for both slots
        int s = tid >> 1, bb = tid & 1;
        sh_tok[s][0][bb] = x[(size_t)(4 * p + 2 * s + bb) * T_SEQ + 0] & 255;
    }

    float* hsout = out;                                 // [B][T][H]
    float* hN    = out + (size_t)LOGITS_ELEMS;          // [B][H]
    float* cN    = hN + BATCH * HID;                    // [B][H]

    for (int t = 0; t < T_SEQ; t++) {
        const int pb = t & 1;
#pragma unroll
        for (int s = 0; s < 2; s++) {
            const int g   = 2 * p + s;                  // group 0..31
            const int bb0 = g * 2;                      // first batch of group

            // ---- wait for all 8 slices of h(t-1) (t>0) ----
            if (t > 0 && tid == 0) {
                for (;;) {
                    uint4 f0 = ld_acq4(&g_flag[g][0]);
                    uint4 f1 = ld_acq4(&g_flag[g][4]);
                    unsigned mn = min(min(min(f0.x, f0.y), min(f0.z, f0.w)),
                                      min(min(f1.x, f1.y), min(f1.z, f1.w)));
                    if (mn >= (unsigned)t) break;
                }
            }
            __syncthreads();

            // ---- stage h(t-1) into skewed smem (L2-only loads) ----
            if (tid < 128) {
                int bb = tid >> 6, k4 = tid & 63;       // k = k4*4
                float4 hv;
                if (t == 0) hv = make_float4(0.f, 0.f, 0.f, 0.f);
                else hv = ldcg4(&hsout[((size_t)(bb0 + bb) * T_SEQ + (t - 1)) * HID + k4 * 4]);
                *reinterpret_cast<float4*>(
                    &sh_h[s][bb][(k4 >> 5) * HPAD + (k4 & 31) * 4]) = hv;
            }
            // prefetch tokens for t+1 of this slot (off critical path)
            if (tid >= 128 && tid < 130 && t + 1 < T_SEQ)
                sh_tok[s][pb ^ 1][tid - 128] =
                    x[(size_t)(bb0 + (tid - 128)) * T_SEQ + t + 1] & 255;
            __syncthreads();

            // ---- token-table contributions (early issue) ----
            float xg0 = 0.f, xg1 = 0.f;
            if (q == 0) {
                xg0 = __ldg(&g_xtab[sh_tok[s][pb][0] * G4 + r_global]);
                xg1 = __ldg(&g_xtab[sh_tok[s][pb][1] * G4 + r_global]);
            }

            // ---- dot products: 2 batches x 128 k, weights in regs ----
            float acc[2];
#pragma unroll
            for (int bb = 0; bb < 2; bb++) {
                unsigned long long a2 = 0ull, b2 = 0ull;
                const ulonglong2* hp =
                    reinterpret_cast<const ulonglong2*>(&sh_h[s][bb][q * HPAD]);
#pragma unroll
                for (int i = 0; i < 32; i++) {
                    ulonglong2 hv = hp[i];
                    ffma2(a2, w2[2 * i],     hv.x);
                    ffma2(b2, w2[2 * i + 1], hv.y);
                }
                float a0, a1, c0, c1;
                upk2(a2, a0, a1);
                upk2(b2, c0, c1);
                acc[bb] = (a0 + a1) + (c0 + c1);
            }
            // reduce across the 2 k-chunks (adjacent lanes)
            acc[0] += __shfl_xor_sync(0xffffffffu, acc[0], 1);
            acc[1] += __shfl_xor_sync(0xffffffffu, acc[1], 1);
            if (q == 0) {
                sh_gates[s][r][0] = acc[0] + xg0;
                sh_gates[s][r][1] = acc[1] + xg1;
            }
            __syncthreads();

            // ---- gate nonlinearities + state update (64 threads) ----
            if (tid < 64) {
                int bb = tid >> 5, j2 = tid & 31;
                float iv = sh_gates[s][j2][bb];
                float fv = sh_gates[s][32 + j2][bb];
                float gv = sh_gates[s][64 + j2][bb];
                float ov = sh_gates[s][96 + j2][bb];
                float is = __fdividef(1.f, 1.f + __expf(-iv));
                float fs = __fdividef(1.f, 1.f + __expf(-fv));
                float gt = 1.f - __fdividef(2.f, 1.f + __expf(2.f * gv));
                float os = __fdividef(1.f, 1.f + __expf(-ov));
                float cv = fs * sh_c[s][bb][j2] + is * gt;
                sh_c[s][bb][j2] = cv;
                float ct = 1.f - __fdividef(2.f, 1.f + __expf(2.f * cv));
                float hv = os * ct;
                hsout[((size_t)(bb0 + bb) * T_SEQ + t) * HID + j_base + j2] = hv;
                if (t == T_SEQ - 1) {
                    hN[(bb0 + bb) * HID + j_base + j2] = hv;
                    cN[(bb0 + bb) * HID + j_base + j2] = cv;
                }
            }
            __syncthreads();                         // all h stores done
            if (tid == 0) st_rel(&g_flag[g][m], (unsigned)(t + 1));
        }
    }
}

// =====================================================================
// Phase 2: logits = hs @ fc_W^T + fc_b, in-place over the hs region.
// Each CTA: 32 rows, 128 threads, 8x8 register tile per thread, f32x2.
// =====================================================================
#define FC_KSLAB 32
#define FC_WPAD  260

__global__ void __launch_bounds__(128)
fc_kernel(float* __restrict__ out, const float* __restrict__ fc_b) {
    __shared__ __align__(16) float wslab[FC_KSLAB][FC_WPAD];  // ~33 KB
    __shared__ float sh_h[32][FC_KSLAB + 1];                  // 4.1 KB

    const int tid = threadIdx.x;
    const int rg  = tid >> 5;            // warp -> rows rg*8 .. +8
    const int cg  = tid & 31;            // cols cg*8 .. +8
    const size_t row_base = (size_t)blockIdx.x * 32;

    unsigned long long acc[8][4];
#pragma unroll
    for (int a = 0; a < 8; a++)
#pragma unroll
        for (int b = 0; b < 4; b++) acc[a][b] = 0ull;

    for (int k0 = 0; k0 < HID; k0 += FC_KSLAB) {
        __syncthreads();
        for (int i = tid; i < FC_KSLAB * 64; i += 128) {
            int kk = i >> 6, c4 = i & 63;
            *reinterpret_cast<float4*>(&wslab[kk][c4 * 4]) =
                *reinterpret_cast<const float4*>(&g_fcwt[(size_t)(k0 + kk) * VOCAB + c4 * 4]);
        }
        for (int i = tid; i < 32 * (FC_KSLAB / 4); i += 128) {
            int rr = i >> 3, k4 = i & 7;
            float4 v = *reinterpret_cast<const float4*>(
                &out[(row_base + rr) * HID + k0 + k4 * 4]);
            sh_h[rr][k4 * 4 + 0] = v.x;
            sh_h[rr][k4 * 4 + 1] = v.y;
            sh_h[rr][k4 * 4 + 2] = v.z;
            sh_h[rr][k4 * 4 + 3] = v.w;
        }
        __syncthreads();
#pragma unroll 4
        for (int kk = 0; kk < FC_KSLAB; kk++) {
            ulonglong2 wv0 = *reinterpret_cast<const ulonglong2*>(&wslab[kk][cg * 8]);
            ulonglong2 wv1 = *reinterpret_cast<const ulonglong2*>(&wslab[kk][cg * 8 + 4]);
#pragma unroll
            for (int rr = 0; rr < 8; rr++) {
                float hv = sh_h[rg * 8 + rr][kk];
                unsigned long long hp = pk2(hv, hv);
                ffma2(acc[rr][0], hp, wv0.x);
                ffma2(acc[rr][1], hp, wv0.y);
                ffma2(acc[rr][2], hp, wv1.x);
                ffma2(acc[rr][3], hp, wv1.y);
            }
        }
    }

    float bias[8];
#pragma unroll
    for (int cc = 0; cc < 8; cc++) bias[cc] = fc_b[cg * 8 + cc];
#pragma unroll
    for (int rr = 0; rr < 8; rr++) {
        float v[8];
        upk2(acc[rr][0], v[0], v[1]);
        upk2(acc[rr][1], v[2], v[3]);
        upk2(acc[rr][2], v[4], v[5]);
        upk2(acc[rr][3], v[6], v[7]);
        float4 o0 = make_float4(v[0] + bias[0], v[1] + bias[1], v[2] + bias[2], v[3] + bias[3]);
        float4 o1 = make_float4(v[4] + bias[4], v[5] + bias[5], v[6] + bias[6], v[7] + bias[7]);
        float* dst = out + (row_base + rg * 8 + rr) * VOCAB + cg * 8;
        *reinterpret_cast<float4*>(dst)     = o0;
        *reinterpret_cast<float4*>(dst + 4) = o1;
    }
}

// =====================================================================
extern "C" void kernel_launch(void* const* d_in, const int* in_sizes, int n_in,
                              void* d_out, int out_size) {
    (void)in_sizes; (void)n_in; (void)out_size;
    const int*   x      = (const int*)d_in[0];     // int32 tokens
    const float* W_ih   = (const float*)d_in[1];
    const float* W_hh   = (const float*)d_in[2];
    const float* b_ih   = (const float*)d_in[3];
    const float* b_hh   = (const float*)d_in[4];
    const float* fc_W   = (const float*)d_in[5];
    const float* fc_b   = (const float*)d_in[6];
    float* out = (float*)d_out;

    prep_kernel<<<1024, 256>>>(W_ih, b_ih, b_hh, fc_W);
    lstm_kernel<<<128, 256>>>(x, W_hh, out);
    fc_kernel<<<(BATCH * T_SEQ) / 32, 128>>>(out, fc_b);
}

// round 8
// speedup vs baseline: 2.2138x; 2.2138x over previous
#include <cuda_runtime.h>
#include <cstdint>

// TinyLSTM: B=64, T=2048, H=256, V=256
// out = [ logits (64*2048*256) | h_n (64*256) | c_n (64*256) ]  (float32)

#define T_SEQ 2048
#define BATCH 64
#define HID   256
#define G4    1024
#define VOCAB 256
#define LOGITS_ELEMS (BATCH * T_SEQ * HID)

#define CLUSTER_N 8
#define CH 36          // skewed chunk stride (floats): chunk kq at kq*36 -> conflict-free

// scratch (static device arrays; no allocation)
__device__ float g_xtab[VOCAB * G4];   // [v][r] = W_ih[r][v] + b_ih[r] + b_hh[r]
__device__ float g_fcwt[HID * VOCAB];  // [k][c] = fc_W[c][k]

// ---- packed f32x2 helpers ----
__device__ __forceinline__ unsigned long long pk2(float a, float b) {
    unsigned long long r;
    asm("mov.b64 %0, {%1, %2};" : "=l"(r) : "f"(a), "f"(b));
    return r;
}
__device__ __forceinline__ void upk2(unsigned long long v, float& a, float& b) {
    asm("mov.b64 {%0, %1}, %2;" : "=f"(a), "=f"(b) : "l"(v));
}
__device__ __forceinline__ void ffma2(unsigned long long& d, unsigned long long a, unsigned long long b) {
    asm("fma.rn.f32x2 %0, %1, %2, %0;" : "+l"(d) : "l"(a), "l"(b));
}
__device__ __forceinline__ uint32_t smem_u32(const void* p) {
    uint32_t a;
    asm("{ .reg .u64 t; cvta.to.shared.u64 t, %1; cvt.u32.u64 %0, t; }" : "=r"(a) : "l"(p));
    return a;
}
// spin-wait (HW sleep) on local mbarrier parity, cluster-scope acquire
__device__ __forceinline__ void bar_wait_cluster(uint32_t addr, unsigned parity) {
    asm volatile(
        "{\n\t"
        ".reg .pred P;\n\t"
        "LW_%=:\n\t"
        "mbarrier.try_wait.parity.acquire.cluster.shared::cta.b64 P, [%0], %1, 0x989680;\n\t"
        "@P bra LD_%=;\n\t"
        "bra LW_%=;\n\t"
        "LD_%=:\n\t"
        "}"
        :: "r"(addr), "r"(parity) : "memory");
}

// =====================================================================
// Phase 0: token table (biases folded), fc_W transpose
// =====================================================================
__global__ void prep_kernel(const float* __restrict__ W_ih,
                            const float* __restrict__ b_ih,
                            const float* __restrict__ b_hh,
                            const float* __restrict__ fc_W) {
    int idx = blockIdx.x * blockDim.x + threadIdx.x;
    if (idx < VOCAB * G4) {
        int v = idx >> 10;
        int r = idx & 1023;
        g_xtab[v * G4 + r] = W_ih[r * VOCAB + v] + b_ih[r] + b_hh[r];
    }
    if (idx < HID * VOCAB) {
        int k = idx >> 8;
        int c = idx & 255;
        g_fcwt[k * VOCAB + c] = fc_W[c * HID + k];
    }
}

// =====================================================================
// Phase 1: persistent LSTM, DSMEM h-exchange via point-to-point mbarriers.
// 16 clusters of 8 CTAs; cluster = batch group (4 batches). Member m owns
// gate columns [m*32, m*32+32) of all four gates. 256 threads = 32 j x
// 8 k-chunks; each thread holds 4 gate rows x 32 k of W_hh in registers
// (w2[64]) and all four gate accumulators -> no smem gate exchange;
// cell state lives in a register. Per step:
//   wait local mbarrier -> matmul (smem h) -> shuffle reduce-scatter ->
//   epilogue in both lanes of each pair (even lane: push h slice into
//   all 8 peers' smem; odd lane: global h store for the FC) ->
//   __syncthreads -> tid0: 8 remote mbarrier.arrive (release.cluster).
// Two-buffer ping-pong is race-free by the dependency chain.
// =====================================================================
__global__ void __launch_bounds__(256, 1) __cluster_dims__(CLUSTER_N, 1, 1)
lstm_kernel(const int* __restrict__ x,
            const float* __restrict__ W_hh,
            float* __restrict__ out) {
    __shared__ __align__(16) float sh_hx[2][4][8 * CH];  // [buf][batch][chunk*CH+j]
    __shared__ __align__(8) unsigned long long bar[2];   // mbarriers (ping-pong)
    __shared__ int sh_tok[2][4];                         // double-buffered tokens

    const int cta    = blockIdx.x;
    const int gb     = cta >> 3;        // batch group / cluster id
    const int m      = cta & 7;         // cluster rank = gate-slice member
    const int b_base = gb * 4;
    const int j_base = m * 32;

    const int tid = threadIdx.x;
    const int j   = tid >> 3;           // local column 0..31
    const int kq  = tid & 7;            // k-chunk 0..7 (32 k each)
    const int bmy = kq >> 1;            // this thread's epilogue batch
    const int row0 = j_base + j;        // gate-0 row; gate g at row0 + g*256

    // --- W_hh slice -> registers: 4 gates x 32 k = 64 f32x2 regs ---
    unsigned long long w2[64];
#pragma unroll
    for (int g = 0; g < 4; g++) {
        const float4* wr = reinterpret_cast<const float4*>(
            W_hh + (size_t)(g * 256 + row0) * HID + kq * 32);
#pragma unroll
        for (int i = 0; i < 8; i++) {
            float4 v = wr[i];
            w2[g * 16 + 2 * i]     = pk2(v.x, v.y);
            w2[g * 16 + 2 * i + 1] = pk2(v.z, v.w);
        }
    }
    // zero both h buffers; init tokens; init mbarriers
    for (int i = tid; i < 2 * 4 * 8 * CH; i += 256)
        (&sh_hx[0][0][0])[i] = 0.0f;
    if (tid < 4) sh_tok[0][tid] = x[(size_t)(b_base + tid) * T_SEQ + 0] & 255;
    if (tid == 0) {
        uint32_t b0 = smem_u32(&bar[0]);
        uint32_t b1 = smem_u32(&bar[1]);
        asm volatile("mbarrier.init.shared.b64 [%0], %1;" :: "r"(b0), "r"(CLUSTER_N) : "memory");
        asm volatile("mbarrier.init.shared.b64 [%0], %1;" :: "r"(b1), "r"(CLUSTER_N) : "memory");
    }
    __syncthreads();
    // all CTAs initialized before any peer DSMEM traffic
    asm volatile("barrier.cluster.arrive.aligned;" ::: "memory");
    asm volatile("barrier.cluster.wait.aligned;"   ::: "memory");

    float* hsout = out;                                 // [B][T][H]
    float* hN    = out + (size_t)LOGITS_ELEMS;          // [B][H]
    float* cN    = hN + BATCH * HID;                    // [B][H]

    const uint32_t bar0a = smem_u32(&bar[0]);
    const uint32_t bar1a = smem_u32(&bar[1]);

    float creg = 0.0f;                                  // cell state for (bmy, row j)
    unsigned par0 = 0, par1 = 0;

    for (int t = 0; t < T_SEQ; t++) {
        const int rb = (t - 1) & 1;     // read buffer (h(t-1))
        const int wb = t & 1;           // write buffer (h(t))
        const int pb = t & 1;           // token buffer

        // ---- wait for h(t-1) from all 8 producers (local mbarrier) ----
        if (t > 0) {
            if (rb) { bar_wait_cluster(bar1a, par1); par1 ^= 1u; }
            else    { bar_wait_cluster(bar0a, par0); par0 ^= 1u; }
        }

        // ---- token-table contributions (early issue, consumed post-reduce) ----
        const int tok = sh_tok[pb][bmy];
        float xg[4];
#pragma unroll
        for (int g = 0; g < 4; g++)
            xg[g] = __ldg(&g_xtab[tok * G4 + g * 256 + row0]);

        // prefetch next tokens (off critical path)
        if (tid < 4 && t + 1 < T_SEQ)
            sh_tok[pb ^ 1][tid] = x[(size_t)(b_base + tid) * T_SEQ + t + 1] & 255;

        // ---- matmul: 4 gates x 4 batches x 32 k, weights in registers ----
        unsigned long long acc2[4][4];
#pragma unroll
        for (int g = 0; g < 4; g++)
#pragma unroll
            for (int b = 0; b < 4; b++) acc2[g][b] = 0ull;

#pragma unroll
        for (int b = 0; b < 4; b++) {
            const ulonglong2* hp =
                reinterpret_cast<const ulonglong2*>(&sh_hx[rb][b][kq * CH]);
            unsigned long long hreg[16];
#pragma unroll
            for (int i = 0; i < 8; i++) {
                ulonglong2 hv = hp[i];
                hreg[2 * i]     = hv.x;
                hreg[2 * i + 1] = hv.y;
            }
#pragma unroll
            for (int g = 0; g < 4; g++)
#pragma unroll
                for (int i = 0; i < 16; i++)
                    ffma2(acc2[g][b], w2[g * 16 + i], hreg[i]);
        }

        // ---- horizontal sums ----
        float af[4][4];
#pragma unroll
        for (int g = 0; g < 4; g++)
#pragma unroll
            for (int b = 0; b < 4; b++) {
                float a0, a1;
                upk2(acc2[g][b], a0, a1);
                af[g][b] = a0 + a1;
            }

        // ---- reduce-scatter over the 8 k-chunks (16 shuffles) ----
        const bool lo = (kq < 4);
        float a2[4][2];
#pragma unroll
        for (int g = 0; g < 4; g++) {
            float s0 = lo ? af[g][2] : af[g][0];
            float s1 = lo ? af[g][3] : af[g][1];
            s0 = __shfl_xor_sync(0xffffffffu, s0, 4);
            s1 = __shfl_xor_sync(0xffffffffu, s1, 4);
            a2[g][0] = (lo ? af[g][0] : af[g][2]) + s0;
            a2[g][1] = (lo ? af[g][1] : af[g][3]) + s1;
        }
        const bool sel = (kq & 2);
        float fin[4];
#pragma unroll
        for (int g = 0; g < 4; g++) {
            float s = sel ? a2[g][0] : a2[g][1];
            s = __shfl_xor_sync(0xffffffffu, s, 2);
            fin[g] = (sel ? a2[g][1] : a2[g][0]) + s;
        }
#pragma unroll
        for (int g = 0; g < 4; g++)
            fin[g] += __shfl_xor_sync(0xffffffffu, fin[g], 1);
        // both lanes of each pair now hold full i,f,g,o for batch bmy

        // ---- epilogue (all 256 threads; pair-redundant) ----
        {
            float iv = fin[0] + xg[0];
            float fv = fin[1] + xg[1];
            float gv = fin[2] + xg[2];
            float ov = fin[3] + xg[3];
            float is = __fdividef(1.f, 1.f + __expf(-iv));
            float fs = __fdividef(1.f, 1.f + __expf(-fv));
            float gt = 1.f - __fdividef(2.f, 1.f + __expf(2.f * gv));
            float os = __fdividef(1.f, 1.f + __expf(-ov));
            creg = fs * creg + is * gt;
            float ct = 1.f - __fdividef(2.f, 1.f + __expf(2.f * creg));
            float hv = os * ct;

            if (kq & 1) {
                // odd lane: global store for the FC (off recurrence path)
                hsout[((size_t)(b_base + bmy) * T_SEQ + t) * HID + row0] = hv;
                if (t == T_SEQ - 1) {
                    hN[(b_base + bmy) * HID + row0] = hv;
                    cN[(b_base + bmy) * HID + row0] = creg;
                }
            } else if (t + 1 < T_SEQ) {
                // even lane: push h into all 8 cluster members' next buffer
                uint32_t dst = smem_u32(&sh_hx[wb][bmy][m * CH + j]);
#pragma unroll
                for (int rk = 0; rk < CLUSTER_N; rk++) {
                    uint32_t pa;
                    asm("mapa.shared::cluster.u32 %0, %1, %2;" : "=r"(pa) : "r"(dst), "r"(rk));
                    asm volatile("st.shared::cluster.f32 [%0], %1;" :: "r"(pa), "f"(hv) : "memory");
                }
            }
        }

        if (t + 1 < T_SEQ) {
            __syncthreads();                // all remote stores issued
            if (tid == 0) {                 // point-to-point release arrivals
                uint32_t ba = (wb ? bar1a : bar0a);
#pragma unroll
                for (int rk = 0; rk < CLUSTER_N; rk++) {
                    uint32_t pa;
                    asm("mapa.shared::cluster.u32 %0, %1, %2;" : "=r"(pa) : "r"(ba), "r"(rk));
                    asm volatile("mbarrier.arrive.shared::cluster.b64 _, [%0];"
                                 :: "r"(pa) : "memory");
                }
            }
        }
    }

    // no CTA may exit while peers' DSMEM traffic could be in flight
    asm volatile("barrier.cluster.arrive.aligned;" ::: "memory");
    asm volatile("barrier.cluster.wait.aligned;"   ::: "memory");
}

// =====================================================================
// Phase 2: logits = hs @ fc_W^T + fc_b, in-place over the hs region.
// Each CTA: 32 rows, 128 threads, 8x8 register tile per thread, f32x2.
// =====================================================================
#define FC_KSLAB 32
#define FC_WPAD  260

__global__ void __launch_bounds__(128)
fc_kernel(float* __restrict__ out, const float* __restrict__ fc_b) {
    __shared__ __align__(16) float wslab[FC_KSLAB][FC_WPAD];  // ~33 KB
    __shared__ float sh_h[32][FC_KSLAB + 1];                  // 4.1 KB

    const int tid = threadIdx.x;
    const int rg  = tid >> 5;
    const int cg  = tid & 31;
    const size_t row_base = (size_t)blockIdx.x * 32;

    unsigned long long acc[8][4];
#pragma unroll
    for (int a = 0; a < 8; a++)
#pragma unroll
        for (int b = 0; b < 4; b++) acc[a][b] = 0ull;

    for (int k0 = 0; k0 < HID; k0 += FC_KSLAB) {
        __syncthreads();
        for (int i = tid; i < FC_KSLAB * 64; i += 128) {
            int kk = i >> 6, c4 = i & 63;
            *reinterpret_cast<float4*>(&wslab[kk][c4 * 4]) =
                *reinterpret_cast<const float4*>(&g_fcwt[(size_t)(k0 + kk) * VOCAB + c4 * 4]);
        }
        for (int i = tid; i < 32 * (FC_KSLAB / 4); i += 128) {
            int rr = i >> 3, k4 = i & 7;
            float4 v = *reinterpret_cast<const float4*>(
                &out[(row_base + rr) * HID + k0 + k4 * 4]);
            sh_h[rr][k4 * 4 + 0] = v.x;
            sh_h[rr][k4 * 4 + 1] = v.y;
            sh_h[rr][k4 * 4 + 2] = v.z;
            sh_h[rr][k4 * 4 + 3] = v.w;
        }
        __syncthreads();
#pragma unroll 4
        for (int kk = 0; kk < FC_KSLAB; kk++) {
            ulonglong2 wv0 = *reinterpret_cast<const ulonglong2*>(&wslab[kk][cg * 8]);
            ulonglong2 wv1 = *reinterpret_cast<const ulonglong2*>(&wslab[kk][cg * 8 + 4]);
#pragma unroll
            for (int rr = 0; rr < 8; rr++) {
                float hv = sh_h[rg * 8 + rr][kk];
                unsigned long long hp = pk2(hv, hv);
                ffma2(acc[rr][0], hp, wv0.x);
                ffma2(acc[rr][1], hp, wv0.y);
                ffma2(acc[rr][2], hp, wv1.x);
                ffma2(acc[rr][3], hp, wv1.y);
            }
        }
    }

    float bias[8];
#pragma unroll
    for (int cc = 0; cc < 8; cc++) bias[cc] = fc_b[cg * 8 + cc];
#pragma unroll
    for (int rr = 0; rr < 8; rr++) {
        float v[8];
        upk2(acc[rr][0], v[0], v[1]);
        upk2(acc[rr][1], v[2], v[3]);
        upk2(acc[rr][2], v[4], v[5]);
        upk2(acc[rr][3], v[6], v[7]);
        float4 o0 = make_float4(v[0] + bias[0], v[1] + bias[1], v[2] + bias[2], v[3] + bias[3]);
        float4 o1 = make_float4(v[4] + bias[4], v[5] + bias[5], v[6] + bias[6], v[7] + bias[7]);
        float* dst = out + (row_base + rg * 8 + rr) * VOCAB + cg * 8;
        *reinterpret_cast<float4*>(dst)     = o0;
        *reinterpret_cast<float4*>(dst + 4) = o1;
    }
}

// =====================================================================
extern "C" void kernel_launch(void* const* d_in, const int* in_sizes, int n_in,
                              void* d_out, int out_size) {
    (void)in_sizes; (void)n_in; (void)out_size;
    const int*   x      = (const int*)d_in[0];     // int32 tokens
    const float* W_ih   = (const float*)d_in[1];
    const float* W_hh   = (const float*)d_in[2];
    const float* b_ih   = (const float*)d_in[3];
    const float* b_hh   = (const float*)d_in[4];
    const float* fc_W   = (const float*)d_in[5];
    const float* fc_b   = (const float*)d_in[6];
    float* out = (float*)d_out;

    prep_kernel<<<1024, 256>>>(W_ih, b_ih, b_hh, fc_W);
    lstm_kernel<<<128, 256>>>(x, W_hh, out);
    fc_kernel<<<(BATCH * T_SEQ) / 32, 128>>>(out, fc_b);
}